// round 9
// baseline (speedup 1.0000x reference)
#include <cuda_runtime.h>
#include <cuda_fp16.h>

#define NN 50000
#define NE 800000
#define NTOT (NE + NN)
#define NF 128
#define NH 256
#define NC 40
#define KHOPS 10

// ---------------- device scratch (static, no runtime alloc) ----------------
__device__ int   g_esrc[NE];
__device__ int   g_edst[NE];
__device__ __align__(16) int g_cnt[NN + 64];   // zero at entry: static init + trailing k_zerocnt
__device__ int   g_ptr[NN + 1];
__device__ float g_dinv[NN];
__device__ __align__(16) int2   g_edge[NTOT];  // {src, w as float bits}
__device__ __align__(16) __half g_h0[NN * NF];
__device__ __align__(16) __half g_h1[NN * NF];
__device__ __align__(16) __half g_hid[NN * NF];
__device__ __align__(16) float  g_z1[(size_t)NN * NH];

// ---------------- launch 1: detect dtype (per block) + convert + count ----
__global__ void k_convert(const void* __restrict__ ei) {
    __shared__ int s_mode;
    if (threadIdx.x < 32) {
        const long long* p = (const long long*)ei;
        int t = threadIdx.x;
        int bad = 0;
#pragma unroll
        for (int j = 0; j < 8; j++) {
            long long v = p[t + j * 32];
            if (v < 0 || v >= NN) bad = 1;
        }
        unsigned m = __ballot_sync(0xFFFFFFFFu, bad);
        if (t == 0) s_mode = (m == 0) ? 1 : 0;
    }
    __syncthreads();
    int mode = s_mode;

    int i = blockIdx.x * blockDim.x + threadIdx.x;
    if (i >= NE) return;
    int s, d;
    if (mode) {
        const long long* p = (const long long*)ei;
        s = (int)p[i];
        d = (int)p[NE + i];
    } else {
        const int* p = (const int*)ei;
        s = p[i];
        d = p[NE + i];
    }
    g_esrc[i] = s;
    g_edst[i] = d;
    if ((unsigned)s < NN && (unsigned)d < NN) atomicAdd(&g_cnt[d], 1);
}

// ---------------- launch 2: scan degrees(+self) -> ptr, dinv, zero cnt ----
__global__ void k_scan() {
    __shared__ int wsum[32];
    __shared__ int s_tot;
    int tid = threadIdx.x, lane = tid & 31, w = tid >> 5;
    int carry = 0;
    const int ITERS = (NN + 4095) / 4096;  // 13
    for (int it = 0; it < ITERS; it++) {
        int base = it * 4096 + tid * 4;
        int c0 = 0, c1 = 0, c2 = 0, c3 = 0;
        if (base + 3 < NN) {
            int4 v = *(const int4*)&g_cnt[base];
            c0 = v.x; c1 = v.y; c2 = v.z; c3 = v.w;
        } else {
            if (base < NN)     c0 = g_cnt[base];
            if (base + 1 < NN) c1 = g_cnt[base + 1];
            if (base + 2 < NN) c2 = g_cnt[base + 2];
            if (base + 3 < NN) c3 = g_cnt[base + 3];
        }
        // degree includes self loop
        int d0 = (base < NN)     ? c0 + 1 : 0;
        int d1 = (base + 1 < NN) ? c1 + 1 : 0;
        int d2 = (base + 2 < NN) ? c2 + 1 : 0;
        int d3 = (base + 3 < NN) ? c3 + 1 : 0;
        int tsum = d0 + d1 + d2 + d3;
        int x = tsum;
#pragma unroll
        for (int off = 1; off < 32; off <<= 1) {
            int y = __shfl_up_sync(0xFFFFFFFFu, x, off);
            if (lane >= off) x += y;
        }
        if (lane == 31) wsum[w] = x;
        __syncthreads();
        if (w == 0) {
            int v = wsum[lane];
            int xx = v;
#pragma unroll
            for (int off = 1; off < 32; off <<= 1) {
                int y = __shfl_up_sync(0xFFFFFFFFu, xx, off);
                if (lane >= off) xx += y;
            }
            if (lane == 31) s_tot = xx;
            wsum[lane] = xx - v;
        }
        __syncthreads();
        int excl = carry + wsum[w] + (x - tsum);
        if (base < NN)     { g_ptr[base]     = excl;                g_dinv[base]     = rsqrtf((float)d0); g_cnt[base]     = 0; }
        if (base + 1 < NN) { g_ptr[base + 1] = excl + d0;           g_dinv[base + 1] = rsqrtf((float)d1); g_cnt[base + 1] = 0; }
        if (base + 2 < NN) { g_ptr[base + 2] = excl + d0 + d1;      g_dinv[base + 2] = rsqrtf((float)d2); g_cnt[base + 2] = 0; }
        if (base + 3 < NN) { g_ptr[base + 3] = excl + d0 + d1 + d2; g_dinv[base + 3] = rsqrtf((float)d3); g_cnt[base + 3] = 0; }
        carry += s_tot;
        __syncthreads();
    }
    if (tid == 0) g_ptr[NN] = carry;
}

// ---------------- launch 3: fill CSR (interleaved int2) + init h ----------
__global__ void k_fill(const float* __restrict__ x, const float* __restrict__ temp) {
    int i = blockIdx.x * blockDim.x + threadIdx.x;
    if (i < NE) {
        unsigned r = (unsigned)g_esrc[i];
        unsigned c = (unsigned)g_edst[i];
        if (r < NN && c < NN) {
            int pos = g_ptr[c] + atomicAdd(&g_cnt[c], 1);
            float w = g_dinv[r] * g_dinv[c];
            g_edge[pos] = make_int2((int)r, __float_as_int(w));
        }
    } else if (i < NTOT) {
        int n = i - NE;
        int pos = g_ptr[n] + atomicAdd(&g_cnt[n], 1);
        float d = g_dinv[n];
        g_edge[pos] = make_int2(n, __float_as_int(d * d));
    }
    // fused h init (grid-stride over float4 feature space)
    for (int j = i; j < NN * NF / 4; j += gridDim.x * blockDim.x) {
        float t0 = __ldg(&temp[0]);
        float4 v = ((const float4*)x)[j];
        __half2 p0 = __floats2half2_rn(v.x, v.y);
        __half2 p1 = __floats2half2_rn(v.z, v.w);
        int2 st;
        st.x = *(int*)&p0; st.y = *(int*)&p1;
        ((int2*)g_h0)[j] = st;
        __half2 q0 = __floats2half2_rn(t0 * v.x, t0 * v.y);
        __half2 q1 = __floats2half2_rn(t0 * v.z, t0 * v.w);
        int2 sh;
        sh.x = *(int*)&q0; sh.y = *(int*)&q1;
        ((int2*)g_hid)[j] = sh;
    }
}

// ---------------- launch 4: re-zero cnt so next invocation starts clean ---
__global__ void k_zerocnt() {
    int i = blockIdx.x * blockDim.x + threadIdx.x;
    if (i < NN) g_cnt[i] = 0;
}

// ---------------- launches 5..14: one hop (warp per node) ------------------
__global__ void k_prop(const float* __restrict__ temp, int k) {
    const __half* __restrict__ hin = (k & 1) ? g_h1 : g_h0;
    __half* __restrict__ hout      = (k & 1) ? g_h0 : g_h1;
    int node = blockIdx.x * 8 + (threadIdx.x >> 5);
    if (node >= NN) return;
    int lane = threadIdx.x & 31;
    int beg = __ldg(&g_ptr[node]), end = __ldg(&g_ptr[node + 1]);
    float tk = __ldg(&temp[k + 1]);

    float a0 = 0.f, a1 = 0.f, a2 = 0.f, a3 = 0.f;
    int e = beg;
    for (; e + 3 < end; e += 4) {
        int2 E0 = __ldg(&g_edge[e]);
        int2 E1 = __ldg(&g_edge[e + 1]);
        int2 E2 = __ldg(&g_edge[e + 2]);
        int2 E3 = __ldg(&g_edge[e + 3]);
        float w0 = __int_as_float(E0.y), w1 = __int_as_float(E1.y);
        float w2 = __int_as_float(E2.y), w3 = __int_as_float(E3.y);
        float2 r0 = __ldg(&((const float2*)(hin + (size_t)E0.x * NF))[lane]);
        float2 r1 = __ldg(&((const float2*)(hin + (size_t)E1.x * NF))[lane]);
        float2 r2 = __ldg(&((const float2*)(hin + (size_t)E2.x * NF))[lane]);
        float2 r3 = __ldg(&((const float2*)(hin + (size_t)E3.x * NF))[lane]);
        {
            float2 fa = __half22float2(*(__half2*)&r0.x);
            float2 fb = __half22float2(*(__half2*)&r0.y);
            a0 += w0 * fa.x; a1 += w0 * fa.y; a2 += w0 * fb.x; a3 += w0 * fb.y;
        }
        {
            float2 fa = __half22float2(*(__half2*)&r1.x);
            float2 fb = __half22float2(*(__half2*)&r1.y);
            a0 += w1 * fa.x; a1 += w1 * fa.y; a2 += w1 * fb.x; a3 += w1 * fb.y;
        }
        {
            float2 fa = __half22float2(*(__half2*)&r2.x);
            float2 fb = __half22float2(*(__half2*)&r2.y);
            a0 += w2 * fa.x; a1 += w2 * fa.y; a2 += w2 * fb.x; a3 += w2 * fb.y;
        }
        {
            float2 fa = __half22float2(*(__half2*)&r3.x);
            float2 fb = __half22float2(*(__half2*)&r3.y);
            a0 += w3 * fa.x; a1 += w3 * fa.y; a2 += w3 * fb.x; a3 += w3 * fb.y;
        }
    }
    for (; e < end; e++) {
        int2 E = __ldg(&g_edge[e]);
        float w = __int_as_float(E.y);
        float2 r = __ldg(&((const float2*)(hin + (size_t)E.x * NF))[lane]);
        float2 fa = __half22float2(*(__half2*)&r.x);
        float2 fb = __half22float2(*(__half2*)&r.y);
        a0 += w * fa.x; a1 += w * fa.y; a2 += w * fb.x; a3 += w * fb.y;
    }

    // store h_{k+1} fp16
    {
        __half2 p0 = __floats2half2_rn(a0, a1);
        __half2 p1 = __floats2half2_rn(a2, a3);
        int2 st;
        st.x = *(int*)&p0; st.y = *(int*)&p1;
        ((int2*)(hout + (size_t)node * NF))[lane] = st;
    }
    // hidden += tk * h_{k+1}  (fp16 storage, fp32 math)
    {
        int2* hid = (int2*)(g_hid + (size_t)node * NF);
        int2 hv = hid[lane];
        float2 f0 = __half22float2(*(__half2*)&hv.x);
        float2 f1 = __half22float2(*(__half2*)&hv.y);
        f0.x += tk * a0; f0.y += tk * a1; f1.x += tk * a2; f1.y += tk * a3;
        __half2 p0 = __floats2half2_rn(f0.x, f0.y);
        __half2 p1 = __floats2half2_rn(f1.x, f1.y);
        hv.x = *(int*)&p0; hv.y = *(int*)&p1;
        hid[lane] = hv;
    }
}

// ---------------- MLP layer 1: z1 = relu(hidden @ W1 + b1) ----------------
__global__ void k_mlp1(const float* __restrict__ B, const float* __restrict__ bias) {
    __shared__ float As[64][33];
    __shared__ float Bs[32][64];
    float* __restrict__ C = g_z1;

    int tid = threadIdx.x;
    int brow = blockIdx.x * 64;
    int bcol = blockIdx.y * 64;
    int tr = (tid / 16) * 4;
    int tc = (tid % 16) * 4;

    float acc[4][4];
#pragma unroll
    for (int i = 0; i < 4; i++)
#pragma unroll
        for (int j = 0; j < 4; j++) acc[i][j] = 0.f;

    for (int k0 = 0; k0 < NF; k0 += 32) {
#pragma unroll
        for (int t = 0; t < 2; t++) {
            int i = tid + t * 256;
            int r = i / 8, c = (i % 8) * 4;
            float2 fa = make_float2(0.f, 0.f), fb = make_float2(0.f, 0.f);
            if (brow + r < NN) {
                int2 raw = *(const int2*)&g_hid[(size_t)(brow + r) * NF + k0 + c];
                fa = __half22float2(*(__half2*)&raw.x);
                fb = __half22float2(*(__half2*)&raw.y);
            }
            As[r][c] = fa.x; As[r][c + 1] = fa.y; As[r][c + 2] = fb.x; As[r][c + 3] = fb.y;
        }
#pragma unroll
        for (int t = 0; t < 2; t++) {
            int i = tid + t * 256;
            int r = i / 16, c = (i % 16) * 4;
            float4 v = *(const float4*)&B[(size_t)(k0 + r) * NH + bcol + c];
            *(float4*)&Bs[r][c] = v;
        }
        __syncthreads();
#pragma unroll
        for (int kk = 0; kk < 32; kk++) {
            float a[4];
#pragma unroll
            for (int i = 0; i < 4; i++) a[i] = As[tr + i][kk];
            float4 b = *(const float4*)&Bs[kk][tc];
#pragma unroll
            for (int i = 0; i < 4; i++) {
                acc[i][0] += a[i] * b.x;
                acc[i][1] += a[i] * b.y;
                acc[i][2] += a[i] * b.z;
                acc[i][3] += a[i] * b.w;
            }
        }
        __syncthreads();
    }

    float4 bb = *(const float4*)&bias[bcol + tc];
#pragma unroll
    for (int i = 0; i < 4; i++) {
        int r = brow + tr + i;
        if (r < NN) {
            float4 v;
            v.x = fmaxf(acc[i][0] + bb.x, 0.f);
            v.y = fmaxf(acc[i][1] + bb.y, 0.f);
            v.z = fmaxf(acc[i][2] + bb.z, 0.f);
            v.w = fmaxf(acc[i][3] + bb.w, 0.f);
            *(float4*)&C[(size_t)r * NH + bcol + tc] = v;
        }
    }
}

// ---------------- MLP layer 2 + log_softmax: thread per node --------------
__global__ void k_mlp2(const float* __restrict__ W2, const float* __restrict__ b2,
                       float* __restrict__ out) {
    __shared__ float Ws[NH * NC];
    __shared__ float bs[NC];
    for (int i = threadIdx.x; i < NH * NC; i += blockDim.x) Ws[i] = W2[i];
    if (threadIdx.x < NC) bs[threadIdx.x] = b2[threadIdx.x];
    __syncthreads();

    int node = blockIdx.x * blockDim.x + threadIdx.x;
    if (node >= NN) return;

    float acc[NC];
#pragma unroll
    for (int j = 0; j < NC; j++) acc[j] = bs[j];

    const float4* z4 = (const float4*)(g_z1 + (size_t)node * NH);
    for (int kk = 0; kk < NH / 4; kk++) {
        float4 z = z4[kk];
        int base = (kk * 4) * NC;
#pragma unroll
        for (int j = 0; j < NC; j++) {
            acc[j] += z.x * Ws[base + j] + z.y * Ws[base + NC + j]
                    + z.z * Ws[base + 2 * NC + j] + z.w * Ws[base + 3 * NC + j];
        }
    }

    float m = -1e30f;
#pragma unroll
    for (int j = 0; j < NC; j++) m = fmaxf(m, acc[j]);
    float s = 0.f;
#pragma unroll
    for (int j = 0; j < NC; j++) s += expf(acc[j] - m);
    float ls = logf(s);
    float* o = out + (size_t)node * NC;
#pragma unroll
    for (int j = 0; j < NC; j++) o[j] = acc[j] - m - ls;
}

// ---------------- launch ----------------
extern "C" void kernel_launch(void* const* d_in, const int* in_sizes, int n_in,
                              void* d_out, int out_size) {
    const float* x    = (const float*)d_in[0];
    const void*  ei   = d_in[1];
    const float* temp = (const float*)d_in[2];
    const float* W1   = (const float*)d_in[3];
    const float* b1   = (const float*)d_in[4];
    const float* W2   = (const float*)d_in[5];
    const float* b2   = (const float*)d_in[6];
    float*       out  = (float*)d_out;

    const int TB = 256;

    k_convert<<<(NE + TB - 1) / TB, TB>>>(ei);               // 1
    k_scan<<<1, 1024>>>();                                   // 2
    k_fill<<<(NTOT + TB - 1) / TB, TB>>>(x, temp);           // 3
    k_zerocnt<<<(NN + TB - 1) / TB, TB>>>();                 // 4  (leaves cnt clean for next call)

    for (int k = 0; k < KHOPS; k++) {                        // 5..14
        k_prop<<<(NN + 7) / 8, 256>>>(temp, k);
    }

    dim3 g1((NN + 63) / 64, NH / 64);
    k_mlp1<<<g1, 256>>>(W1, b1);                             // 15
    k_mlp2<<<(NN + 127) / 128, 128>>>(W2, b2, out);          // 16
}